// round 2
// baseline (speedup 1.0000x reference)
#include <cuda_runtime.h>
#include <math.h>

#define NL 3
#define WIDTH 4
#define H 512
#define B 32
#define S 512
#define SP (S + 2*WIDTH)      // 520
#define CIN ((WIDTH+1)*H)     // 2560
#define BSR (B*S)             // 16384 rows

// ---------------- scratch (no allocation allowed -> __device__ globals) ----------------
__device__ __align__(256) float g_pad[2][(size_t)B*SP*H];   // padded sequences, per direction
__device__ __align__(256) float g_x [2][(size_t)BSR*H];     // conv output / hw pong
__device__ __align__(256) float g_x2[2][(size_t)BSR*H];     // hw ping

// ---------------- pad kernel: build [B, S+8, H] padded sequence ----------------
__global__ void pad_kernel(const float* __restrict__ inputs,
                           const float* __restrict__ fwd_pads,
                           const float* __restrict__ bwd_pads,
                           int layer, int use_inputs)
{
    int dir = blockIdx.y;
    long idx = (long)blockIdx.x * blockDim.x + threadIdx.x;   // float4 granularity
    const long n4 = (long)B * SP * H / 4;
    if (idx >= n4) return;
    long e = idx * 4;
    int h = (int)(e % H);
    long bp = e / H;
    int p = (int)(bp % SP);
    int b = (int)(bp / SP);

    const float* src = use_inputs ? inputs : g_x[dir];
    float4 v;
    if (p < WIDTH) {
        v = *(const float4*)&fwd_pads[((long)layer*WIDTH + p)*H + h];
    } else if (p >= S + WIDTH) {
        v = *(const float4*)&bwd_pads[((long)layer*WIDTH + (p - S - WIDTH))*H + h];
    } else {
        v = *(const float4*)&src[((long)b*S + (p - WIDTH))*H + h];
    }
    *(float4*)&g_pad[dir][((long)b*SP + p)*H + h] = v;
}

// ---------------- conv GEMM: y = relu(A @ W + bias), A gathered from padded seq ----------------
// M=16384, N=512, K=2560.  Tiles: BM=128, BN=128, BK=8. 256 threads, 8x8 microtile.
#define CBM 128
#define CBN 128
#define CBK 8

__global__ __launch_bounds__(256)
void conv_gemm_kernel(const float* __restrict__ fwd_W, const float* __restrict__ bwd_W,
                      const float* __restrict__ fwd_b, const float* __restrict__ bwd_b,
                      int layer)
{
    int dir = blockIdx.z;
    const float* Wm   = (dir ? bwd_W : fwd_W) + (long)layer * CIN * H;
    const float* bias = (dir ? bwd_b : fwd_b) + (long)layer * H;
    const float* pad  = g_pad[dir];
    const int off = dir ? WIDTH : 0;   // fwd window: padded[t+k]; bwd: padded[t+4+k]

    const int rowTile = blockIdx.y;            // 0..127
    const int colTile = blockIdx.x;            // 0..3
    const int b  = (rowTile * CBM) / S;        // 4 row tiles per batch (128 | 512)
    const int t0 = (rowTile * CBM) % S;
    const long padRowBase = ((long)b * SP + t0 + off) * H;
    const int n0 = colTile * CBN;

    __shared__ __align__(16) float As[CBK][CBM];
    __shared__ __align__(16) float Bs[CBK][CBN];

    const int tid  = threadIdx.x;
    const int aRow = tid >> 1;                 // 0..127
    const int aK4  = (tid & 1) * 4;            // 0 or 4
    const int bK   = tid >> 5;                 // 0..7
    const int bN   = (tid & 31) * 4;           // 0..124
    const int tx   = tid & 15;                 // col group (8 cols)
    const int ty   = tid >> 4;                 // row group (8 rows)

    float acc[8][8];
#pragma unroll
    for (int i = 0; i < 8; i++)
#pragma unroll
        for (int j = 0; j < 8; j++) acc[i][j] = 0.0f;

    for (int kk0 = 0; kk0 < CIN; kk0 += CBK) {
        // A tile: row aRow, K cols kk0+aK4 .. +3. Window index w = kk>>9, h = kk&511.
        {
            int kk = kk0 + aK4;
            int w  = kk >> 9;
            int h  = kk & (H - 1);
            float4 av = *(const float4*)&pad[padRowBase + (long)(aRow + w) * H + h];
            As[aK4 + 0][aRow] = av.x;
            As[aK4 + 1][aRow] = av.y;
            As[aK4 + 2][aRow] = av.z;
            As[aK4 + 3][aRow] = av.w;
        }
        // B tile: W[(kk0+bK), n0+bN .. +3]
        *(float4*)&Bs[bK][bN] = *(const float4*)&Wm[(long)(kk0 + bK) * H + n0 + bN];
        __syncthreads();

#pragma unroll
        for (int k = 0; k < CBK; k++) {
            float4 a0 = *(const float4*)&As[k][ty * 8];
            float4 a1 = *(const float4*)&As[k][ty * 8 + 4];
            float4 b0 = *(const float4*)&Bs[k][tx * 8];
            float4 b1 = *(const float4*)&Bs[k][tx * 8 + 4];
            float a[8] = {a0.x, a0.y, a0.z, a0.w, a1.x, a1.y, a1.z, a1.w};
            float bb[8] = {b0.x, b0.y, b0.z, b0.w, b1.x, b1.y, b1.z, b1.w};
#pragma unroll
            for (int i = 0; i < 8; i++)
#pragma unroll
                for (int j = 0; j < 8; j++)
                    acc[i][j] = fmaf(a[i], bb[j], acc[i][j]);
        }
        __syncthreads();
    }

    // epilogue: relu(acc + bias) -> g_x[dir]
    float* xo = g_x[dir];
#pragma unroll
    for (int i = 0; i < 8; i++) {
        long r = (long)rowTile * CBM + ty * 8 + i;
#pragma unroll
        for (int j4 = 0; j4 < 8; j4 += 4) {
            int c = n0 + tx * 8 + j4;
            float4 v;
            v.x = fmaxf(acc[i][j4 + 0] + bias[c + 0], 0.0f);
            v.y = fmaxf(acc[i][j4 + 1] + bias[c + 1], 0.0f);
            v.z = fmaxf(acc[i][j4 + 2] + bias[c + 2], 0.0f);
            v.w = fmaxf(acc[i][j4 + 3] + bias[c + 3], 0.0f);
            *(float4*)&xo[r * H + c] = v;
        }
    }
}

// ---------------- highway step GEMM with fused gate epilogue ----------------
// proj = x @ W[512,1024] + b; nl = proj[:, :512], gate = proj[:, 512:]
// x_out = sigmoid(gate)*x + (1-sigmoid(gate))*relu(nl)
// Tiles: BM=128 rows, BN=64 output cols, dual accumulators (nl + gate). 256 threads, 8x4 microtile x2.
__global__ __launch_bounds__(256)
void hw_kernel(const float* __restrict__ fwd_hw_W, const float* __restrict__ fwd_hw_b,
               const float* __restrict__ bwd_hw_W, const float* __restrict__ bwd_hw_b,
               int layer, int step, float* __restrict__ out)
{
    int dir = blockIdx.z;
    const float* Wm = (dir ? bwd_hw_W : fwd_hw_W) + ((long)layer * 2 + step) * (long)H * 2 * H;
    const float* hb = (dir ? bwd_hw_b : fwd_hw_b) + ((long)layer * 2 + step) * 2 * H;
    const float* src = step ? g_x2[dir] : g_x[dir];
    float*       dst = step ? g_x [dir] : g_x2[dir];

    const int rowTile = blockIdx.y;        // 0..127
    const int colTile = blockIdx.x;        // 0..7
    const int row0 = rowTile * 128;
    const int n0   = colTile * 64;

    __shared__ __align__(16) float As[8][128];
    __shared__ __align__(16) float Bn[8][64];
    __shared__ __align__(16) float Bg[8][64];

    const int tid  = threadIdx.x;
    const int aRow = tid >> 1;
    const int aK4  = (tid & 1) * 4;
    const int tx   = tid & 15;             // 4 cols each
    const int ty   = tid >> 4;             // 8 rows each

    float accn[8][4], accg[8][4];
#pragma unroll
    for (int i = 0; i < 8; i++)
#pragma unroll
        for (int j = 0; j < 4; j++) { accn[i][j] = 0.0f; accg[i][j] = 0.0f; }

    for (int kk0 = 0; kk0 < H; kk0 += 8) {
        float4 av = *(const float4*)&src[(long)(row0 + aRow) * H + kk0 + aK4];
        As[aK4 + 0][aRow] = av.x;
        As[aK4 + 1][aRow] = av.y;
        As[aK4 + 2][aRow] = av.z;
        As[aK4 + 3][aRow] = av.w;
        if (tid < 128) {
            int bk = tid >> 4, bn = (tid & 15) * 4;
            *(float4*)&Bn[bk][bn] = *(const float4*)&Wm[(long)(kk0 + bk) * (2 * H) + n0 + bn];
        } else {
            int t2 = tid - 128;
            int bk = t2 >> 4, bn = (t2 & 15) * 4;
            *(float4*)&Bg[bk][bn] = *(const float4*)&Wm[(long)(kk0 + bk) * (2 * H) + H + n0 + bn];
        }
        __syncthreads();

#pragma unroll
        for (int k = 0; k < 8; k++) {
            float4 a0 = *(const float4*)&As[k][ty * 8];
            float4 a1 = *(const float4*)&As[k][ty * 8 + 4];
            float a[8] = {a0.x, a0.y, a0.z, a0.w, a1.x, a1.y, a1.z, a1.w};
            float4 bnv = *(const float4*)&Bn[k][tx * 4];
            float4 bgv = *(const float4*)&Bg[k][tx * 4];
            float bn[4] = {bnv.x, bnv.y, bnv.z, bnv.w};
            float bg[4] = {bgv.x, bgv.y, bgv.z, bgv.w};
#pragma unroll
            for (int i = 0; i < 8; i++)
#pragma unroll
                for (int j = 0; j < 4; j++) {
                    accn[i][j] = fmaf(a[i], bn[j], accn[i][j]);
                    accg[i][j] = fmaf(a[i], bg[j], accg[i][j]);
                }
        }
        __syncthreads();
    }

    // epilogue: highway combine
#pragma unroll
    for (int i = 0; i < 8; i++) {
        long r = (long)row0 + ty * 8 + i;
#pragma unroll
        for (int j = 0; j < 4; j++) {
            int c = n0 + tx * 4 + j;
            float xi = src[r * H + c];
            float nl = accn[i][j] + hb[c];
            float gt = accg[i][j] + hb[H + c];
            float g  = 1.0f / (1.0f + expf(-gt));
            float v  = g * xi + (1.0f - g) * fmaxf(nl, 0.0f);
            dst[r * H + c] = v;
            if (out) out[((long)layer * BSR + r) * (2 * H) + (long)dir * H + c] = v;
        }
    }
}

// ---------------- launch ----------------
extern "C" void kernel_launch(void* const* d_in, const int* in_sizes, int n_in,
                              void* d_out, int out_size)
{
    const float* inputs   = (const float*)d_in[0];
    // d_in[1] = mask (int32), unused by the reference
    const float* fwd_pads = (const float*)d_in[2];
    const float* bwd_pads = (const float*)d_in[3];
    const float* fwd_W    = (const float*)d_in[4];
    const float* fwd_b    = (const float*)d_in[5];
    const float* bwd_W    = (const float*)d_in[6];
    const float* bwd_b    = (const float*)d_in[7];
    const float* fwd_hw_W = (const float*)d_in[8];
    const float* fwd_hw_b = (const float*)d_in[9];
    const float* bwd_hw_W = (const float*)d_in[10];
    const float* bwd_hw_b = (const float*)d_in[11];
    float* out = (float*)d_out;

    const long n4 = (long)B * SP * H / 4;
    dim3 gp((unsigned)((n4 + 255) / 256), 2, 1);
    dim3 gc(H / CBN, BSR / CBM, 2);     // 4 x 128 x 2
    dim3 gh(H / 64, BSR / 128, 2);      // 8 x 128 x 2

    for (int layer = 0; layer < NL; layer++) {
        pad_kernel<<<gp, 256>>>(inputs, fwd_pads, bwd_pads, layer, layer == 0 ? 1 : 0);
        conv_gemm_kernel<<<gc, 256>>>(fwd_W, bwd_W, fwd_b, bwd_b, layer);
        hw_kernel<<<gh, 256>>>(fwd_hw_W, fwd_hw_b, bwd_hw_W, bwd_hw_b, layer, 0, nullptr);
        hw_kernel<<<gh, 256>>>(fwd_hw_W, fwd_hw_b, bwd_hw_W, bwd_hw_b, layer, 1, out);
    }
}

// round 3
// speedup vs baseline: 3.2714x; 3.2714x over previous
#include <cuda_runtime.h>
#include <math.h>

#define NL 3
#define WIDTH 4
#define H 512
#define B 32
#define S 512
#define SP (S + 2*WIDTH)      // 520
#define CIN ((WIDTH+1)*H)     // 2560
#define BSR (B*S)             // 16384

#define ASTR 36               // A smem row stride (words) -> conflict-free frag loads
#define BSTR 136              // B smem row stride (words) -> conflict-free frag loads

// ---------------- scratch ----------------
__device__ __align__(256) float g_pad[2][(size_t)B*SP*H];
__device__ __align__(256) float g_x [2][(size_t)BSR*H];
__device__ __align__(256) float g_x2[2][(size_t)BSR*H];

__device__ __forceinline__ unsigned f2tf(float f) {
    unsigned u;
    asm("cvt.rna.tf32.f32 %0, %1;" : "=r"(u) : "f"(f));
    return u;
}

__device__ __forceinline__ void mma_tf32(float* d, const unsigned* a, const unsigned* b) {
    asm volatile("mma.sync.aligned.m16n8k8.row.col.f32.tf32.tf32.f32 "
        "{%0,%1,%2,%3}, {%4,%5,%6,%7}, {%8,%9}, {%0,%1,%2,%3};\n"
        : "+f"(d[0]), "+f"(d[1]), "+f"(d[2]), "+f"(d[3])
        : "r"(a[0]), "r"(a[1]), "r"(a[2]), "r"(a[3]), "r"(b[0]), "r"(b[1]));
}

// ---------------- pad kernel ----------------
__global__ void pad_kernel(const float* __restrict__ inputs,
                           const float* __restrict__ fwd_pads,
                           const float* __restrict__ bwd_pads,
                           int layer, int use_inputs)
{
    int dir = blockIdx.y;
    long idx = (long)blockIdx.x * blockDim.x + threadIdx.x;
    const long n4 = (long)B * SP * H / 4;
    if (idx >= n4) return;
    long e = idx * 4;
    int h = (int)(e % H);
    long bp = e / H;
    int p = (int)(bp % SP);
    int b = (int)(bp / SP);

    const float* src = use_inputs ? inputs : g_x[dir];
    float4 v;
    if (p < WIDTH) {
        v = *(const float4*)&fwd_pads[((long)layer*WIDTH + p)*H + h];
    } else if (p >= S + WIDTH) {
        v = *(const float4*)&bwd_pads[((long)layer*WIDTH + (p - S - WIDTH))*H + h];
    } else {
        v = *(const float4*)&src[((long)b*S + (p - WIDTH))*H + h];
    }
    *(float4*)&g_pad[dir][((long)b*SP + p)*H + h] = v;
}

// ---------------- conv GEMM (tf32 tensor cores) ----------------
// y = relu(A_win @ W + bias).  M=16384, N=512, K=2560. Block 128x128, BK=32.
__global__ __launch_bounds__(256, 2)
void conv_gemm_kernel(const float* __restrict__ fwd_W, const float* __restrict__ bwd_W,
                      const float* __restrict__ fwd_b, const float* __restrict__ bwd_b,
                      int layer)
{
    __shared__ unsigned As[128 * ASTR];
    __shared__ unsigned Bs[32 * BSTR];

    const int dir = blockIdx.z;
    const float* Wm   = (dir ? bwd_W : fwd_W) + (long)layer * CIN * H;
    const float* bias = (dir ? bwd_b : fwd_b) + (long)layer * H;
    const float* pad  = g_pad[dir];
    const int off = dir ? WIDTH : 0;

    const int rowTile = blockIdx.y;
    const int colTile = blockIdx.x;
    const int bb = (rowTile * 128) / S;
    const int t0 = (rowTile * 128) % S;
    const long padRowBase = ((long)bb * SP + t0 + off) * H;
    const int n0 = colTile * 128;

    const int tid  = threadIdx.x;
    const int lane = tid & 31;
    const int warp = tid >> 5;
    const int wm   = warp >> 2;   // 0..1  (64 rows each)
    const int wn   = warp & 3;    // 0..3  (32 cols each)
    const int g    = lane >> 2;
    const int tig  = lane & 3;

    float d[4][4][4];
#pragma unroll
    for (int i = 0; i < 4; i++)
#pragma unroll
        for (int j = 0; j < 4; j++)
#pragma unroll
            for (int k = 0; k < 4; k++) d[i][j][k] = 0.0f;

    // staging index maps (float4 granularity)
    int aRow[4], aC[4], bK[4], bC[4];
#pragma unroll
    for (int i = 0; i < 4; i++) {
        int idx = tid + i * 256;
        aRow[i] = idx >> 3; aC[i] = (idx & 7) * 4;   // A: 128 rows x 32 cols
        bK[i]  = idx >> 5;  bC[i] = (idx & 31) * 4;  // B: 32 k x 128 n
    }

    float4 pa[4], pb[4];
    // prologue: stage 0
#pragma unroll
    for (int i = 0; i < 4; i++)
        pa[i] = *(const float4*)&pad[padRowBase + (long)aRow[i] * H + aC[i]];
#pragma unroll
    for (int i = 0; i < 4; i++)
        pb[i] = *(const float4*)&Wm[(long)bK[i] * H + n0 + bC[i]];
#pragma unroll
    for (int i = 0; i < 4; i++) {
        *(uint4*)&As[aRow[i]*ASTR + aC[i]] =
            make_uint4(f2tf(pa[i].x), f2tf(pa[i].y), f2tf(pa[i].z), f2tf(pa[i].w));
        *(uint4*)&Bs[bK[i]*BSTR + bC[i]] =
            make_uint4(f2tf(pb[i].x), f2tf(pb[i].y), f2tf(pb[i].z), f2tf(pb[i].w));
    }
    __syncthreads();

    const int NS = CIN / 32;  // 80
    for (int s = 0; s < NS; s++) {
        const bool more = (s + 1) < NS;
        if (more) {
            int k0 = (s + 1) * 32;
            int w  = k0 >> 9;
            int h0 = k0 & (H - 1);
#pragma unroll
            for (int i = 0; i < 4; i++)
                pa[i] = *(const float4*)&pad[padRowBase + (long)(aRow[i] + w) * H + h0 + aC[i]];
#pragma unroll
            for (int i = 0; i < 4; i++)
                pb[i] = *(const float4*)&Wm[(long)(k0 + bK[i]) * H + n0 + bC[i]];
        }
        // compute current stage
#pragma unroll
        for (int ks = 0; ks < 4; ks++) {
            const int kb = ks * 8;
            unsigned af[4][4], bf[4][2];
#pragma unroll
            for (int mf = 0; mf < 4; mf++) {
                int r = wm * 64 + mf * 16;
                af[mf][0] = As[(r + g    ) * ASTR + kb + tig    ];
                af[mf][1] = As[(r + g + 8) * ASTR + kb + tig    ];
                af[mf][2] = As[(r + g    ) * ASTR + kb + tig + 4];
                af[mf][3] = As[(r + g + 8) * ASTR + kb + tig + 4];
            }
#pragma unroll
            for (int nf = 0; nf < 4; nf++) {
                int c = wn * 32 + nf * 8 + g;
                bf[nf][0] = Bs[(kb + tig    ) * BSTR + c];
                bf[nf][1] = Bs[(kb + tig + 4) * BSTR + c];
            }
#pragma unroll
            for (int mf = 0; mf < 4; mf++)
#pragma unroll
                for (int nf = 0; nf < 4; nf++)
                    mma_tf32(d[mf][nf], af[mf], bf[nf]);
        }
        __syncthreads();
        if (more) {
#pragma unroll
            for (int i = 0; i < 4; i++) {
                *(uint4*)&As[aRow[i]*ASTR + aC[i]] =
                    make_uint4(f2tf(pa[i].x), f2tf(pa[i].y), f2tf(pa[i].z), f2tf(pa[i].w));
                *(uint4*)&Bs[bK[i]*BSTR + bC[i]] =
                    make_uint4(f2tf(pb[i].x), f2tf(pb[i].y), f2tf(pb[i].z), f2tf(pb[i].w));
            }
            __syncthreads();
        }
    }

    // epilogue: relu(acc + bias)
    float* xo = g_x[dir];
#pragma unroll
    for (int mf = 0; mf < 4; mf++) {
        long r0 = (long)rowTile * 128 + wm * 64 + mf * 16 + g;
#pragma unroll
        for (int nf = 0; nf < 4; nf++) {
            int c = n0 + wn * 32 + nf * 8 + 2 * tig;
            float b0 = bias[c], b1 = bias[c + 1];
            float2 v0, v1;
            v0.x = fmaxf(d[mf][nf][0] + b0, 0.f);
            v0.y = fmaxf(d[mf][nf][1] + b1, 0.f);
            v1.x = fmaxf(d[mf][nf][2] + b0, 0.f);
            v1.y = fmaxf(d[mf][nf][3] + b1, 0.f);
            *(float2*)&xo[r0 * H + c]       = v0;
            *(float2*)&xo[(r0 + 8) * H + c] = v1;
        }
    }
}

// ---------------- highway GEMM (tf32, interleaved nl/gate) ----------------
// Block: 128 rows x 64 outputs (128 smem cols: even=nonlin, odd=gate). K=512, BK=32.
__global__ __launch_bounds__(256, 2)
void hw_kernel(const float* __restrict__ fwd_hw_W, const float* __restrict__ fwd_hw_b,
               const float* __restrict__ bwd_hw_W, const float* __restrict__ bwd_hw_b,
               int layer, int step, float* __restrict__ out)
{
    __shared__ unsigned As[128 * ASTR];
    __shared__ unsigned Bs[32 * BSTR];

    const int dir = blockIdx.z;
    const float* Wm = (dir ? bwd_hw_W : fwd_hw_W) + ((long)layer * 2 + step) * (long)H * 2 * H;
    const float* hb = (dir ? bwd_hw_b : fwd_hw_b) + ((long)layer * 2 + step) * 2 * H;
    const float* src = step ? g_x2[dir] : g_x[dir];
    float*       dst = step ? g_x [dir] : g_x2[dir];

    const int row0 = blockIdx.y * 128;
    const int n0   = blockIdx.x * 64;    // output columns

    const int tid  = threadIdx.x;
    const int lane = tid & 31;
    const int warp = tid >> 5;
    const int wm   = warp >> 2;   // 0..1
    const int wn   = warp & 3;    // 0..3 (16 outputs each)
    const int g    = lane >> 2;
    const int tig  = lane & 3;

    float d[4][4][4];
#pragma unroll
    for (int i = 0; i < 4; i++)
#pragma unroll
        for (int j = 0; j < 4; j++)
#pragma unroll
            for (int k = 0; k < 4; k++) d[i][j][k] = 0.0f;

    int aRow[4], aC[4], bK[4], bJ[4];
#pragma unroll
    for (int i = 0; i < 4; i++) {
        int idx = tid + i * 256;
        aRow[i] = idx >> 3; aC[i] = (idx & 7) * 4;
        bK[i]  = idx >> 5;  bJ[i] = (idx & 31);      // output-pair index 0..31 (2 outputs each)
    }

    float4 pa[4]; float2 pn[4], pg[4];
#pragma unroll
    for (int i = 0; i < 4; i++)
        pa[i] = *(const float4*)&src[(long)(row0 + aRow[i]) * H + aC[i]];
#pragma unroll
    for (int i = 0; i < 4; i++) {
        pn[i] = *(const float2*)&Wm[(long)bK[i] * (2*H) + n0 + 2*bJ[i]];
        pg[i] = *(const float2*)&Wm[(long)bK[i] * (2*H) + H + n0 + 2*bJ[i]];
    }
#pragma unroll
    for (int i = 0; i < 4; i++) {
        *(uint4*)&As[aRow[i]*ASTR + aC[i]] =
            make_uint4(f2tf(pa[i].x), f2tf(pa[i].y), f2tf(pa[i].z), f2tf(pa[i].w));
        *(uint4*)&Bs[bK[i]*BSTR + 4*bJ[i]] =
            make_uint4(f2tf(pn[i].x), f2tf(pg[i].x), f2tf(pn[i].y), f2tf(pg[i].y));
    }
    __syncthreads();

    const int NS = H / 32;  // 16
    for (int s = 0; s < NS; s++) {
        const bool more = (s + 1) < NS;
        if (more) {
            int k0 = (s + 1) * 32;
#pragma unroll
            for (int i = 0; i < 4; i++)
                pa[i] = *(const float4*)&src[(long)(row0 + aRow[i]) * H + k0 + aC[i]];
#pragma unroll
            for (int i = 0; i < 4; i++) {
                pn[i] = *(const float2*)&Wm[(long)(k0 + bK[i]) * (2*H) + n0 + 2*bJ[i]];
                pg[i] = *(const float2*)&Wm[(long)(k0 + bK[i]) * (2*H) + H + n0 + 2*bJ[i]];
            }
        }
#pragma unroll
        for (int ks = 0; ks < 4; ks++) {
            const int kb = ks * 8;
            unsigned af[4][4], bf[4][2];
#pragma unroll
            for (int mf = 0; mf < 4; mf++) {
                int r = wm * 64 + mf * 16;
                af[mf][0] = As[(r + g    ) * ASTR + kb + tig    ];
                af[mf][1] = As[(r + g + 8) * ASTR + kb + tig    ];
                af[mf][2] = As[(r + g    ) * ASTR + kb + tig + 4];
                af[mf][3] = As[(r + g + 8) * ASTR + kb + tig + 4];
            }
#pragma unroll
            for (int nf = 0; nf < 4; nf++) {
                int c = wn * 32 + nf * 8 + g;
                bf[nf][0] = Bs[(kb + tig    ) * BSTR + c];
                bf[nf][1] = Bs[(kb + tig + 4) * BSTR + c];
            }
#pragma unroll
            for (int mf = 0; mf < 4; mf++)
#pragma unroll
                for (int nf = 0; nf < 4; nf++)
                    mma_tf32(d[mf][nf], af[mf], bf[nf]);
        }
        __syncthreads();
        if (more) {
#pragma unroll
            for (int i = 0; i < 4; i++) {
                *(uint4*)&As[aRow[i]*ASTR + aC[i]] =
                    make_uint4(f2tf(pa[i].x), f2tf(pa[i].y), f2tf(pa[i].z), f2tf(pa[i].w));
                *(uint4*)&Bs[bK[i]*BSTR + 4*bJ[i]] =
                    make_uint4(f2tf(pn[i].x), f2tf(pg[i].x), f2tf(pn[i].y), f2tf(pg[i].y));
            }
            __syncthreads();
        }
    }

    // epilogue: highway combine. smem col pair (2j, 2j+1) = (nonlin, gate) of output j.
#pragma unroll
    for (int mf = 0; mf < 4; mf++) {
        long r0 = (long)row0 + wm * 64 + mf * 16 + g;
#pragma unroll
        for (int nf = 0; nf < 4; nf++) {
            int j = n0 + wn * 16 + nf * 4 + tig;
            float bn = hb[j], bg = hb[H + j];
#pragma unroll
            for (int half = 0; half < 2; half++) {
                long r = r0 + half * 8;
                float nl = d[mf][nf][half * 2 + 0] + bn;
                float gt = d[mf][nf][half * 2 + 1] + bg;
                float xi = src[r * H + j];
                float gs = 1.0f / (1.0f + expf(-gt));
                float v  = gs * xi + (1.0f - gs) * fmaxf(nl, 0.0f);
                dst[r * H + j] = v;
                if (out) out[((long)layer * BSR + r) * (2 * H) + (long)dir * H + j] = v;
            }
        }
    }
}

// ---------------- launch ----------------
extern "C" void kernel_launch(void* const* d_in, const int* in_sizes, int n_in,
                              void* d_out, int out_size)
{
    const float* inputs   = (const float*)d_in[0];
    const float* fwd_pads = (const float*)d_in[2];
    const float* bwd_pads = (const float*)d_in[3];
    const float* fwd_W    = (const float*)d_in[4];
    const float* fwd_b    = (const float*)d_in[5];
    const float* bwd_W    = (const float*)d_in[6];
    const float* bwd_b    = (const float*)d_in[7];
    const float* fwd_hw_W = (const float*)d_in[8];
    const float* fwd_hw_b = (const float*)d_in[9];
    const float* bwd_hw_W = (const float*)d_in[10];
    const float* bwd_hw_b = (const float*)d_in[11];
    float* out = (float*)d_out;

    const long n4 = (long)B * SP * H / 4;
    dim3 gp((unsigned)((n4 + 255) / 256), 2, 1);
    dim3 gc(H / 128, BSR / 128, 2);     // 4 x 128 x 2
    dim3 gh(H / 64, BSR / 128, 2);      // 8 x 128 x 2

    for (int layer = 0; layer < NL; layer++) {
        pad_kernel<<<gp, 256>>>(inputs, fwd_pads, bwd_pads, layer, layer == 0 ? 1 : 0);
        conv_gemm_kernel<<<gc, 256>>>(fwd_W, bwd_W, fwd_b, bwd_b, layer);
        hw_kernel<<<gh, 256>>>(fwd_hw_W, fwd_hw_b, bwd_hw_W, bwd_hw_b, layer, 0, nullptr);
        hw_kernel<<<gh, 256>>>(fwd_hw_W, fwd_hw_b, bwd_hw_W, bwd_hw_b, layer, 1, out);
    }
}